// round 8
// baseline (speedup 1.0000x reference)
#include <cuda_runtime.h>
#include <cuda_fp16.h>
#include <cstdint>

#define BATCH 8192
#define SEQ   40
#define HID   256
#define VOCAB 128
#define NCTA  256

// ===========================================================================
// Global scratch (no cudaMalloc allowed)
// ===========================================================================
__device__ __align__(16) uint4 g_Afrag[2][16384][32];  // A frags, ping-pong
__device__ __align__(16) uint4 g_Bfrag[2048][32];      // B frags (Wh hi/lo)
__device__ float g_c[BATCH * HID];
__device__ float g_Wxb[128 * 1024];
__device__ float g_hfin[BATCH * HID];
__device__ int   g_inT[SEQ * BATCH];
__device__ int   g_bar;                                // grid barrier counter

__device__ __forceinline__ uint32_t smem_to_u32(const void* p) {
    uint32_t a;
    asm("{ .reg .u64 tmp; cvta.to.shared.u64 tmp, %1; cvt.u32.u64 %0, tmp; }"
        : "=r"(a) : "l"(p));
    return a;
}

#define CP_ASYNC16(dst, src) \
    asm volatile("cp.async.cg.shared.global [%0], [%1], 16;" \
        :: "r"(dst), "l"(src) : "memory")
#define CP_COMMIT() asm volatile("cp.async.commit_group;" ::: "memory")
#define CP_WAIT0()  asm volatile("cp.async.wait_group 0;" ::: "memory")

#define LDS128(r0, r1, r2, r3, addr) \
    asm volatile("ld.shared.v4.b32 {%0,%1,%2,%3}, [%4];" \
        : "=r"(r0), "=r"(r1), "=r"(r2), "=r"(r3) : "r"(addr))

#define MMA16816(d, a, b0, b1) \
    asm volatile("mma.sync.aligned.m16n8k16.row.col.f32.f16.f16.f32 " \
        "{%0,%1,%2,%3}, {%4,%5,%6,%7}, {%8,%9}, {%0,%1,%2,%3};" \
        : "+f"((d)[0]), "+f"((d)[1]), "+f"((d)[2]), "+f"((d)[3]) \
        : "r"((a)[0]), "r"((a)[1]), "r"((a)[2]), "r"((a)[3]), \
          "r"(b0), "r"(b1))

__device__ __forceinline__ float sigf(float x) {
    return 1.0f / (1.0f + __expf(-x));
}
__device__ __forceinline__ float tanh_(float x) {
    float ax = fabsf(x);
    float e  = __expf(-2.0f * ax);
    float r  = (1.0f - e) / (1.0f + e);
    return copysignf(r, x);
}

// ===========================================================================
// Prep kernels
// ===========================================================================
__global__ void prep_wh_kernel(const float* __restrict__ Wh) {
    int e = blockIdx.x * blockDim.x + threadIdx.x;  // 0 .. 262143
    int k = e >> 10, col = e & 1023;
    float v = Wh[e];
    __half hi = __float2half(v);
    __half lo = __float2half(v - __half2float(hi));
    int gate = col >> 8, j = col & 255;
    int jt = j >> 5, jw = (j >> 3) & 3, nl = j & 7;
    int kc = k >> 5, ks = (k >> 4) & 1, kk = k & 15;
    int gp = gate >> 1, gs = gate & 1;
    int lane = nl * 4 + ((kk & 7) >> 1);
    int reg  = kk >> 3;
    int hp   = kk & 1;
    int block = (jt * 4 + jw) * 64 + kc * 8 + ks * 4 + gp;
    __half* base = (__half*)g_Bfrag;
    size_t idx0 = ((size_t)block * 32 + lane) * 8 + gs * 4 + reg * 2 + hp;
    size_t idx1 = ((size_t)(block + 2) * 32 + lane) * 8 + gs * 4 + reg * 2 + hp;
    base[idx0] = hi;
    base[idx1] = lo;
}

__global__ void prep_wxb_kernel(const float* __restrict__ Wx,
                                const float* __restrict__ bias) {
    int e = blockIdx.x * blockDim.x + threadIdx.x;  // 0 .. 131071
    g_Wxb[e] = Wx[e] + bias[e & 1023];
}

__global__ void prep_in_kernel(const int* __restrict__ inputs) {
    int i = blockIdx.x * blockDim.x + threadIdx.x;  // 0 .. 327679
    int b = i / SEQ, tt = i - b * SEQ;
    g_inT[tt * BATCH + b] = inputs[i];
}

__global__ void init_state_kernel() {
    int i = blockIdx.x * blockDim.x + threadIdx.x;   // 0 .. 524287
    ((uint4*)g_Afrag[0])[i] = make_uint4(0, 0, 0, 0);
    ((float4*)g_c)[i] = make_float4(0.f, 0.f, 0.f, 0.f);
    if (i == 0) g_bar = 0;
}

// ===========================================================================
// Persistent LSTM: all 40 steps in one launch, grid barrier between steps.
// 256 CTAs x 256 thr; CTA c: jt = c>>5 (fixed B slice), 4 bx tiles/step.
// Per tile: A (64 batch x K x hi/lo = 64KB) staged via cp.async.cg (L2 path);
// B frags LDG'd (L1-resident across steps); warp tile M=32 x (4g x 8j).
// ===========================================================================
#define SMEM_TOTAL 65536

__global__ __launch_bounds__(256, 2) void lstm_persist_kernel() {
    extern __shared__ __align__(16) unsigned char smem[];
    const uint32_t sA = smem_to_u32(smem);
    const int tid  = threadIdx.x;
    const int lane = tid & 31, wid = tid >> 5;
    const int mw = wid >> 2;              // 0..1
    const int jw = wid & 3;               // 0..3
    const int jt  = blockIdx.x >> 5;      // 0..7
    const int bxg = blockIdx.x & 31;      // 0..31
    const int gq = lane >> 2, t4 = lane & 3;

    const uint4* __restrict__ Bp = &g_Bfrag[(jt * 4 + jw) * 64][lane];
    const int jcol = jt * 32 + jw * 8 + t4 * 2;   // even
    const int blk_base = jt * 4 + (jw >> 1) * 2;
    const uint32_t aoff0 = sA + ((mw * 2 + 0) * 32) * 512 + lane * 16;
    const uint32_t aoff1 = sA + ((mw * 2 + 1) * 32) * 512 + lane * 16;

#pragma unroll 1
    for (int t = 0; t < SEQ; t++) {
        const uint4* __restrict__ Ain =
            (const uint4*)g_Afrag[t & 1];
        uint32_t* __restrict__ Aout = (uint32_t*)g_Afrag[(t + 1) & 1];

        // stage A for tile q=0
        {
            const uint4* Asrc = Ain + (size_t)(bxg * 4) * 128 * 32;
#pragma unroll
            for (int i = 0; i < 16; i++)
                CP_ASYNC16(sA + tid * 16 + i * 4096,
                           (const char*)(Asrc + i * 256 + tid));
            CP_COMMIT();
        }

#pragma unroll 1
        for (int q = 0; q < 4; q++) {
            const int bx = bxg * 4 + q;

            // prefetch chars for this tile's epilogue
            int ch[2][2];
#pragma unroll
            for (int mt = 0; mt < 2; mt++)
#pragma unroll
                for (int rr = 0; rr < 2; rr++)
                    ch[mt][rr] = g_inT[t * BATCH + bx * 64 + mw * 32
                                       + mt * 16 + gq + rr * 8];

            // prefetch B iter 0 (L1 hit after first step)
            uint4 bv0 = Bp[0], bv1 = Bp[32], bv2 = Bp[64], bv3 = Bp[96];

            CP_WAIT0();
            __syncthreads();

            float acc[2][4][4];
#pragma unroll
            for (int mt = 0; mt < 2; mt++)
#pragma unroll
                for (int g = 0; g < 4; g++)
#pragma unroll
                    for (int e = 0; e < 4; e++) acc[mt][g][e] = 0.0f;

#pragma unroll 2
            for (int it = 0; it < 16; it++) {
                uint4 bn0, bn1, bn2, bn3;
                if (it < 15) {
                    const uint4* p = Bp + (it + 1) * 128;
                    bn0 = p[0]; bn1 = p[32]; bn2 = p[64]; bn3 = p[96];
                } else {
                    bn0 = bv0; bn1 = bv1; bn2 = bv2; bn3 = bv3;
                }

                uint32_t ah[2][4], al[2][4];
                {
                    uint32_t o = it * 1024;
                    LDS128(ah[0][0], ah[0][1], ah[0][2], ah[0][3], aoff0 + o);
                    LDS128(al[0][0], al[0][1], al[0][2], al[0][3], aoff0 + o + 512);
                    LDS128(ah[1][0], ah[1][1], ah[1][2], ah[1][3], aoff1 + o);
                    LDS128(al[1][0], al[1][1], al[1][2], al[1][3], aoff1 + o + 512);
                }

#pragma unroll
                for (int mt = 0; mt < 2; mt++) {
                    MMA16816(acc[mt][0], ah[mt], bv0.x, bv0.y);
                    MMA16816(acc[mt][1], ah[mt], bv0.z, bv0.w);
                    MMA16816(acc[mt][2], ah[mt], bv1.x, bv1.y);
                    MMA16816(acc[mt][3], ah[mt], bv1.z, bv1.w);
                    MMA16816(acc[mt][0], ah[mt], bv2.x, bv2.y);
                    MMA16816(acc[mt][1], ah[mt], bv2.z, bv2.w);
                    MMA16816(acc[mt][2], ah[mt], bv3.x, bv3.y);
                    MMA16816(acc[mt][3], ah[mt], bv3.z, bv3.w);
                    MMA16816(acc[mt][0], al[mt], bv0.x, bv0.y);
                    MMA16816(acc[mt][1], al[mt], bv0.z, bv0.w);
                    MMA16816(acc[mt][2], al[mt], bv1.x, bv1.y);
                    MMA16816(acc[mt][3], al[mt], bv1.z, bv1.w);
                }
                bv0 = bn0; bv1 = bn1; bv2 = bn2; bv3 = bn3;
            }

            __syncthreads();   // all warps done reading A(q) from smem

            // stage A for tile q+1 (overlaps epilogue)
            if (q < 3) {
                const uint4* Asrc = Ain + (size_t)(bx + 1) * 128 * 32;
#pragma unroll
                for (int i = 0; i < 16; i++)
                    CP_ASYNC16(sA + tid * 16 + i * 4096,
                               (const char*)(Asrc + i * 256 + tid));
                CP_COMMIT();
            }

            // ---- epilogue
#pragma unroll
            for (int mt = 0; mt < 2; mt++) {
                const int grp = bx * 4 + mw * 2 + mt;
#pragma unroll
                for (int rr = 0; rr < 2; rr++) {
                    const int b = bx * 64 + mw * 32 + mt * 16 + gq + rr * 8;
                    const float* wrow = g_Wxb + (size_t)ch[mt][rr] * 1024;
                    float2 wx2[4];
#pragma unroll
                    for (int g = 0; g < 4; g++)
                        wx2[g] = *(const float2*)&wrow[g * 256 + jcol];
                    float2 c2 = *(const float2*)&g_c[(size_t)b * HID + jcol];

                    float cn[2], hn[2];
#pragma unroll
                    for (int e = 0; e < 2; e++) {
                        float zi = acc[mt][0][rr * 2 + e] + (e ? wx2[0].y : wx2[0].x);
                        float zf = acc[mt][1][rr * 2 + e] + (e ? wx2[1].y : wx2[1].x);
                        float zg = acc[mt][2][rr * 2 + e] + (e ? wx2[2].y : wx2[2].x);
                        float zo = acc[mt][3][rr * 2 + e] + (e ? wx2[3].y : wx2[3].x);
                        float ig = sigf(zi), fg = sigf(zf);
                        float gg = tanh_(zg), og = sigf(zo);
                        float cold = e ? c2.y : c2.x;
                        float cc = fg * cold + ig * gg;
                        cn[e] = cc;
                        hn[e] = og * tanh_(cc);
                    }
                    *(float2*)&g_c[(size_t)b * HID + jcol] = make_float2(cn[0], cn[1]);

                    __half h0 = __float2half(hn[0]), h1 = __float2half(hn[1]);
                    __half l0 = __float2half(hn[0] - __half2float(h0));
                    __half l1 = __float2half(hn[1] - __half2float(h1));
                    __half2 phi = __halves2half2(h0, h1);
                    __half2 plo = __halves2half2(l0, l1);
                    const int reg = rr + 2 * (jw & 1);
                    uint32_t idx_hi =
                        (uint32_t)(((grp * 32 + blk_base + 0) * 32 + lane) * 4 + reg);
                    uint32_t idx_lo =
                        (uint32_t)(((grp * 32 + blk_base + 1) * 32 + lane) * 4 + reg);
                    Aout[idx_hi] = *(uint32_t*)&phi;
                    Aout[idx_lo] = *(uint32_t*)&plo;

                    if (t == SEQ - 1)
                        *(float2*)&g_hfin[(size_t)b * HID + jcol] =
                            make_float2(hn[0], hn[1]);
                }
            }
        }

        // ---- grid barrier between steps (monotonic counter)
        __threadfence();
        __syncthreads();
        if (tid == 0) {
            atomicAdd(&g_bar, 1);
            const int target = NCTA * (t + 1);
            int v;
            do {
                asm volatile("ld.acquire.gpu.global.b32 %0, [%1];"
                             : "=r"(v) : "l"(&g_bar));
                if (v < target) __nanosleep(64);
            } while (v < target);
        }
        __syncthreads();
    }
}

// ===========================================================================
// Dense + softmax (reads g_hfin, float)
// ===========================================================================
#define DROWS 8

__global__ __launch_bounds__(128) void dense_softmax_kernel(
    const float* __restrict__ Wd,   // [256, 128]
    const float* __restrict__ bd,   // [128]
    float*       __restrict__ out)  // [BATCH, 128]
{
    const int b0  = blockIdx.x * DROWS;
    const int tid = threadIdx.x;

    __shared__ float hs[DROWS][HID];
    __shared__ float ls[DROWS][VOCAB];

#pragma unroll
    for (int s = 0; s < DROWS * HID / 128; s++) {
        int e = tid + s * 128;
        hs[e >> 8][e & 255] = g_hfin[(size_t)b0 * HID + e];
    }
    __syncthreads();

    float acc[DROWS];
    float bv = bd[tid];
#pragma unroll
    for (int r = 0; r < DROWS; r++) acc[r] = bv;

#pragma unroll 8
    for (int k = 0; k < HID; k++) {
        float w = Wd[k * VOCAB + tid];
#pragma unroll
        for (int r = 0; r < DROWS; r++) acc[r] += hs[r][k] * w;
    }

#pragma unroll
    for (int r = 0; r < DROWS; r++) ls[r][tid] = acc[r];
    __syncthreads();

    const int w = tid >> 5, lane = tid & 31;
#pragma unroll
    for (int rr = 0; rr < 2; rr++) {
        int r = w * 2 + rr;
        float v[4];
        float m = -1e30f;
#pragma unroll
        for (int q = 0; q < 4; q++) {
            v[q] = ls[r][lane + q * 32];
            m = fmaxf(m, v[q]);
        }
#pragma unroll
        for (int o = 16; o > 0; o >>= 1) m = fmaxf(m, __shfl_xor_sync(0xffffffffu, m, o));
        float s = 0.0f;
#pragma unroll
        for (int q = 0; q < 4; q++) {
            v[q] = __expf(v[q] - m);
            s += v[q];
        }
#pragma unroll
        for (int o = 16; o > 0; o >>= 1) s += __shfl_xor_sync(0xffffffffu, s, o);
        float inv = 1.0f / s;
#pragma unroll
        for (int q = 0; q < 4; q++)
            out[(b0 + r) * VOCAB + lane + q * 32] = v[q] * inv;
    }
}

// ===========================================================================
extern "C" void kernel_launch(void* const* d_in, const int* in_sizes, int n_in,
                              void* d_out, int out_size) {
    const int*   inputs = (const int*)d_in[0];
    const float* Wx     = (const float*)d_in[1];
    const float* Wh     = (const float*)d_in[2];
    const float* b      = (const float*)d_in[3];
    const float* Wd     = (const float*)d_in[4];
    const float* bd     = (const float*)d_in[5];
    float*       out    = (float*)d_out;

    cudaFuncSetAttribute(lstm_persist_kernel,
                         cudaFuncAttributeMaxDynamicSharedMemorySize, SMEM_TOTAL);

    init_state_kernel<<<2048, 256>>>();
    prep_wh_kernel<<<1024, 256>>>(Wh);
    prep_wxb_kernel<<<512, 256>>>(Wx, b);
    prep_in_kernel<<<(BATCH * SEQ + 255) / 256, 256>>>(inputs);

    lstm_persist_kernel<<<NCTA, 256, SMEM_TOTAL>>>();

    dense_softmax_kernel<<<BATCH / DROWS, 128>>>(Wd, bd, out);
}

// round 9
// speedup vs baseline: 1.3482x; 1.3482x over previous
#include <cuda_runtime.h>
#include <cuda_fp16.h>
#include <cstdint>

#define BATCH 8192
#define SEQ   40
#define HID   256
#define VOCAB 128

// ===========================================================================
// Global scratch (no cudaMalloc allowed)
// ===========================================================================
// A fragments (h state, single fp16 plane), ping-pong.
// block = grp*16 + kc*2 + ks; grp = batch/16, kc = k/32, ks = (k/16)&1.
// Each block: 32 lanes x uint4 (4 mma a-regs).
__device__ __align__(16) uint4 g_Afrag[2][8192][32];
// B fragments (Wh split hi/lo). block = (jt*4+jw)*64 + (kc*2+ks)*4 + pl*2 + gp.
__device__ __align__(16) uint4 g_Bfrag[2048][32];
__device__ float g_c[BATCH * HID];
__device__ float g_Wxb[128 * 1024];
__device__ float g_hfin[BATCH * HID];
__device__ int   g_inT[SEQ * BATCH];

__device__ __forceinline__ uint32_t smem_to_u32(const void* p) {
    uint32_t a;
    asm("{ .reg .u64 tmp; cvta.to.shared.u64 tmp, %1; cvt.u32.u64 %0, tmp; }"
        : "=r"(a) : "l"(p));
    return a;
}

#define CP_ASYNC16(dst, src) \
    asm volatile("cp.async.cg.shared.global [%0], [%1], 16;" \
        :: "r"(dst), "l"(src) : "memory")
#define CP_COMMIT() asm volatile("cp.async.commit_group;" ::: "memory")
#define CP_WAIT0()  asm volatile("cp.async.wait_group 0;" ::: "memory")

#define LDS128(r0, r1, r2, r3, addr) \
    asm volatile("ld.shared.v4.b32 {%0,%1,%2,%3}, [%4];" \
        : "=r"(r0), "=r"(r1), "=r"(r2), "=r"(r3) : "r"(addr))

#define MMA16816(d, a, b0, b1) \
    asm volatile("mma.sync.aligned.m16n8k16.row.col.f32.f16.f16.f32 " \
        "{%0,%1,%2,%3}, {%4,%5,%6,%7}, {%8,%9}, {%0,%1,%2,%3};" \
        : "+f"((d)[0]), "+f"((d)[1]), "+f"((d)[2]), "+f"((d)[3]) \
        : "r"((a)[0]), "r"((a)[1]), "r"((a)[2]), "r"((a)[3]), \
          "r"(b0), "r"(b1))

__device__ __forceinline__ float sigf(float x) {
    return 1.0f / (1.0f + __expf(-x));
}
__device__ __forceinline__ float tanh_(float x) {
    float ax = fabsf(x);
    float e  = __expf(-2.0f * ax);
    float r  = (1.0f - e) / (1.0f + e);
    return copysignf(r, x);
}

// ===========================================================================
// Prep kernels
// ===========================================================================
__global__ void prep_wh_kernel(const float* __restrict__ Wh) {
    int e = blockIdx.x * blockDim.x + threadIdx.x;  // 0 .. 262143
    int k = e >> 10, col = e & 1023;
    float v = Wh[e];
    __half hi = __float2half(v);
    __half lo = __float2half(v - __half2float(hi));
    int gate = col >> 8, j = col & 255;
    int jt = j >> 5, jw = (j >> 3) & 3, nl = j & 7;
    int kc = k >> 5, ks = (k >> 4) & 1, kk = k & 15;
    int gp = gate >> 1, gs = gate & 1;
    int lane = nl * 4 + ((kk & 7) >> 1);
    int reg  = kk >> 3;
    int hp   = kk & 1;
    int block = (jt * 4 + jw) * 64 + kc * 8 + ks * 4 + gp;
    __half* base = (__half*)g_Bfrag;
    size_t idx0 = ((size_t)block * 32 + lane) * 8 + gs * 4 + reg * 2 + hp;
    size_t idx1 = ((size_t)(block + 2) * 32 + lane) * 8 + gs * 4 + reg * 2 + hp;
    base[idx0] = hi;
    base[idx1] = lo;
}

__global__ void prep_wxb_kernel(const float* __restrict__ Wx,
                                const float* __restrict__ bias) {
    int e = blockIdx.x * blockDim.x + threadIdx.x;  // 0 .. 131071
    g_Wxb[e] = Wx[e] + bias[e & 1023];
}

__global__ void prep_in_kernel(const int* __restrict__ inputs) {
    int i = blockIdx.x * blockDim.x + threadIdx.x;  // 0 .. 327679
    int b = i / SEQ, tt = i - b * SEQ;
    g_inT[tt * BATCH + b] = inputs[i];
}

__global__ void init_state_kernel() {
    int i = blockIdx.x * blockDim.x + threadIdx.x;   // 0 .. 524287
    if (i < 8192 * 32)
        ((uint4*)g_Afrag[0])[i] = make_uint4(0, 0, 0, 0);
    ((float4*)g_c)[i] = make_float4(0.f, 0.f, 0.f, 0.f);
}

// ===========================================================================
// LSTM step. CTA 256 thr = 8 warps (2 mw x 4 jw); warp tile M=32 x (4g x 8j).
// 2-pass: z = a_fp16 * (B_hi + B_lo). A tile (64 batch x K = 32KB) staged in
// SMEM once via cp.async; B frags LDG'd with register double-buffer.
// ===========================================================================
#define SMEM_TOTAL 32768

__global__ __launch_bounds__(256, 2) void lstm_step_kernel(int t) {
    extern __shared__ __align__(16) unsigned char smem[];
    const uint32_t sA = smem_to_u32(smem);
    const int tid  = threadIdx.x;
    const int lane = tid & 31, wid = tid >> 5;
    const int mw = wid >> 2;          // 0..1
    const int jw = wid & 3;           // 0..3
    const int bx = blockIdx.x;        // 0..127
    const int jt = blockIdx.y;        // 0..7

    // ---- stage A tile (64 blocks = 4 batch-groups) into SMEM: 2048 uint4
    {
        const uint4* Asrc = &g_Afrag[t & 1][bx * 64][0];
#pragma unroll
        for (int i = 0; i < 8; i++)
            CP_ASYNC16(sA + tid * 16 + i * 4096,
                       (const char*)(Asrc + i * 256 + tid));
        CP_COMMIT();
    }

    // ---- prefetch chars while A streams
    const int gq = lane >> 2, t4 = lane & 3;
    int ch[2][2];
#pragma unroll
    for (int mt = 0; mt < 2; mt++)
#pragma unroll
        for (int rr = 0; rr < 2; rr++)
            ch[mt][rr] = g_inT[t * BATCH + bx * 64 + mw * 32 + mt * 16 + gq + rr * 8];

    // ---- prefetch B iter 0
    const uint4* __restrict__ Bp = &g_Bfrag[(jt * 4 + jw) * 64][lane];
    uint4 bv0 = Bp[0], bv1 = Bp[32], bv2 = Bp[64], bv3 = Bp[96];

    CP_WAIT0();
    __syncthreads();

    float acc[2][4][4];
#pragma unroll
    for (int mt = 0; mt < 2; mt++)
#pragma unroll
        for (int g = 0; g < 4; g++)
#pragma unroll
            for (int e = 0; e < 4; e++) acc[mt][g][e] = 0.0f;

    // A smem: block (mw*2+mt)*16 + it, 512B/block
    const uint32_t aoff0 = sA + (mw * 2 + 0) * 16 * 512 + lane * 16;
    const uint32_t aoff1 = sA + (mw * 2 + 1) * 16 * 512 + lane * 16;

#pragma unroll 2
    for (int it = 0; it < 16; it++) {
        uint4 bn0, bn1, bn2, bn3;
        if (it < 15) {
            const uint4* p = Bp + (it + 1) * 128;
            bn0 = p[0]; bn1 = p[32]; bn2 = p[64]; bn3 = p[96];
        } else {
            bn0 = bv0; bn1 = bv1; bn2 = bv2; bn3 = bv3;
        }

        uint32_t ah[2][4];
        {
            uint32_t o = it * 512;
            LDS128(ah[0][0], ah[0][1], ah[0][2], ah[0][3], aoff0 + o);
            LDS128(ah[1][0], ah[1][1], ah[1][2], ah[1][3], aoff1 + o);
        }

#pragma unroll
        for (int mt = 0; mt < 2; mt++) {
            MMA16816(acc[mt][0], ah[mt], bv0.x, bv0.y);   // B hi
            MMA16816(acc[mt][1], ah[mt], bv0.z, bv0.w);
            MMA16816(acc[mt][2], ah[mt], bv1.x, bv1.y);
            MMA16816(acc[mt][3], ah[mt], bv1.z, bv1.w);
            MMA16816(acc[mt][0], ah[mt], bv2.x, bv2.y);   // B lo
            MMA16816(acc[mt][1], ah[mt], bv2.z, bv2.w);
            MMA16816(acc[mt][2], ah[mt], bv3.x, bv3.y);
            MMA16816(acc[mt][3], ah[mt], bv3.z, bv3.w);
        }
        bv0 = bn0; bv1 = bn1; bv2 = bn2; bv3 = bn3;
    }

    // ---- Epilogue: z = acc + Wxb[char] -> gates -> c; h stored as A-frags.
    const int jcol = jt * 32 + jw * 8 + t4 * 2;   // even
    // store block = grp*16 + jt*2 + (jw>>1); reg = rr + 2*(jw&1); lane==lane.
    const int blk_base = jt * 2 + (jw >> 1);
    uint32_t* __restrict__ Aout = (uint32_t*)g_Afrag[(t + 1) & 1];

#pragma unroll
    for (int mt = 0; mt < 2; mt++) {
        const int grp = bx * 4 + mw * 2 + mt;
#pragma unroll
        for (int rr = 0; rr < 2; rr++) {
            const int b = bx * 64 + mw * 32 + mt * 16 + gq + rr * 8;
            const float* wrow = g_Wxb + (size_t)ch[mt][rr] * 1024;
            float2 wx2[4];
#pragma unroll
            for (int g = 0; g < 4; g++)
                wx2[g] = *(const float2*)&wrow[g * 256 + jcol];
            float2 c2 = *(const float2*)&g_c[(size_t)b * HID + jcol];

            float cn[2], hn[2];
#pragma unroll
            for (int e = 0; e < 2; e++) {
                float zi = acc[mt][0][rr * 2 + e] + (e ? wx2[0].y : wx2[0].x);
                float zf = acc[mt][1][rr * 2 + e] + (e ? wx2[1].y : wx2[1].x);
                float zg = acc[mt][2][rr * 2 + e] + (e ? wx2[2].y : wx2[2].x);
                float zo = acc[mt][3][rr * 2 + e] + (e ? wx2[3].y : wx2[3].x);
                float ig = sigf(zi), fg = sigf(zf);
                float gg = tanh_(zg), og = sigf(zo);
                float cold = e ? c2.y : c2.x;
                float cc = fg * cold + ig * gg;
                cn[e] = cc;
                hn[e] = og * tanh_(cc);
            }
            *(float2*)&g_c[(size_t)b * HID + jcol] = make_float2(cn[0], cn[1]);

            __half2 phi = __halves2half2(__float2half(hn[0]), __float2half(hn[1]));
            const int reg = rr + 2 * (jw & 1);
            uint32_t idx = (uint32_t)(((grp * 16 + blk_base) * 32 + lane) * 4 + reg);
            Aout[idx] = *(uint32_t*)&phi;

            if (t == SEQ - 1)
                *(float2*)&g_hfin[(size_t)b * HID + jcol] = make_float2(hn[0], hn[1]);
        }
    }
}

// ===========================================================================
// Dense + softmax (reads g_hfin, float)
// ===========================================================================
#define DROWS 8

__global__ __launch_bounds__(128) void dense_softmax_kernel(
    const float* __restrict__ Wd,   // [256, 128]
    const float* __restrict__ bd,   // [128]
    float*       __restrict__ out)  // [BATCH, 128]
{
    const int b0  = blockIdx.x * DROWS;
    const int tid = threadIdx.x;

    __shared__ float hs[DROWS][HID];
    __shared__ float ls[DROWS][VOCAB];

#pragma unroll
    for (int s = 0; s < DROWS * HID / 128; s++) {
        int e = tid + s * 128;
        hs[e >> 8][e & 255] = g_hfin[(size_t)b0 * HID + e];
    }
    __syncthreads();

    float acc[DROWS];
    float bv = bd[tid];
#pragma unroll
    for (int r = 0; r < DROWS; r++) acc[r] = bv;

#pragma unroll 8
    for (int k = 0; k < HID; k++) {
        float w = Wd[k * VOCAB + tid];
#pragma unroll
        for (int r = 0; r < DROWS; r++) acc[r] += hs[r][k] * w;
    }

#pragma unroll
    for (int r = 0; r < DROWS; r++) ls[r][tid] = acc[r];
    __syncthreads();

    const int w = tid >> 5, lane = tid & 31;
#pragma unroll
    for (int rr = 0; rr < 2; rr++) {
        int r = w * 2 + rr;
        float v[4];
        float m = -1e30f;
#pragma unroll
        for (int q = 0; q < 4; q++) {
            v[q] = ls[r][lane + q * 32];
            m = fmaxf(m, v[q]);
        }
#pragma unroll
        for (int o = 16; o > 0; o >>= 1) m = fmaxf(m, __shfl_xor_sync(0xffffffffu, m, o));
        float s = 0.0f;
#pragma unroll
        for (int q = 0; q < 4; q++) {
            v[q] = __expf(v[q] - m);
            s += v[q];
        }
#pragma unroll
        for (int o = 16; o > 0; o >>= 1) s += __shfl_xor_sync(0xffffffffu, s, o);
        float inv = 1.0f / s;
#pragma unroll
        for (int q = 0; q < 4; q++)
            out[(b0 + r) * VOCAB + lane + q * 32] = v[q] * inv;
    }
}

// ===========================================================================
extern "C" void kernel_launch(void* const* d_in, const int* in_sizes, int n_in,
                              void* d_out, int out_size) {
    const int*   inputs = (const int*)d_in[0];
    const float* Wx     = (const float*)d_in[1];
    const float* Wh     = (const float*)d_in[2];
    const float* b      = (const float*)d_in[3];
    const float* Wd     = (const float*)d_in[4];
    const float* bd     = (const float*)d_in[5];
    float*       out    = (float*)d_out;

    cudaFuncSetAttribute(lstm_step_kernel,
                         cudaFuncAttributeMaxDynamicSharedMemorySize, SMEM_TOTAL);

    init_state_kernel<<<2048, 256>>>();
    prep_wh_kernel<<<1024, 256>>>(Wh);
    prep_wxb_kernel<<<512, 256>>>(Wx, b);
    prep_in_kernel<<<(BATCH * SEQ + 255) / 256, 256>>>(inputs);

    dim3 grid(BATCH / 64, 8);  // 128 x 8 = 1024 CTAs
    for (int t = 0; t < SEQ; t++)
        lstm_step_kernel<<<grid, 256, SMEM_TOTAL>>>(t);

    dense_softmax_kernel<<<BATCH / DROWS, 128>>>(Wd, bd, out);
}

// round 10
// speedup vs baseline: 1.8939x; 1.4047x over previous
#include <cuda_runtime.h>
#include <cuda_fp16.h>
#include <cstdint>

#define BATCH 8192
#define SEQ   40
#define HID   256
#define VOCAB 128

// ===========================================================================
// Global scratch (no cudaMalloc allowed)
// ===========================================================================
// A fragments (h state, single fp16 plane), ping-pong.
// block = grp*16 + kc*2 + ks; grp = batch/16, kc = k/32, ks = (k/16)&1.
// Each block: 32 lanes x uint4 (4 mma a-regs).
__device__ __align__(16) uint4 g_Afrag[2][8192][32];
// B fragments (Wh single fp16 plane).
// block = (jt*4+jw)*32 + it*2 + gp,  it = kc*2+ks (0..15), gp = gate pair.
__device__ __align__(16) uint4 g_Bfrag[1024][32];
__device__ float g_c[BATCH * HID];
__device__ float g_Wxb[128 * 1024];
__device__ float g_hfin[BATCH * HID];
__device__ int   g_inT[SEQ * BATCH];

__device__ __forceinline__ uint32_t smem_to_u32(const void* p) {
    uint32_t a;
    asm("{ .reg .u64 tmp; cvta.to.shared.u64 tmp, %1; cvt.u32.u64 %0, tmp; }"
        : "=r"(a) : "l"(p));
    return a;
}

#define CP_ASYNC16(dst, src) \
    asm volatile("cp.async.cg.shared.global [%0], [%1], 16;" \
        :: "r"(dst), "l"(src) : "memory")
#define CP_COMMIT() asm volatile("cp.async.commit_group;" ::: "memory")
#define CP_WAIT0()  asm volatile("cp.async.wait_group 0;" ::: "memory")

#define LDS128(r0, r1, r2, r3, addr) \
    asm volatile("ld.shared.v4.b32 {%0,%1,%2,%3}, [%4];" \
        : "=r"(r0), "=r"(r1), "=r"(r2), "=r"(r3) : "r"(addr))

#define MMA16816(d, a, b0, b1) \
    asm volatile("mma.sync.aligned.m16n8k16.row.col.f32.f16.f16.f32 " \
        "{%0,%1,%2,%3}, {%4,%5,%6,%7}, {%8,%9}, {%0,%1,%2,%3};" \
        : "+f"((d)[0]), "+f"((d)[1]), "+f"((d)[2]), "+f"((d)[3]) \
        : "r"((a)[0]), "r"((a)[1]), "r"((a)[2]), "r"((a)[3]), \
          "r"(b0), "r"(b1))

__device__ __forceinline__ float sigf(float x) {
    return 1.0f / (1.0f + __expf(-x));
}
__device__ __forceinline__ float tanh_(float x) {
    float ax = fabsf(x);
    float e  = __expf(-2.0f * ax);
    float r  = (1.0f - e) / (1.0f + e);
    return copysignf(r, x);
}

// ===========================================================================
// Prep kernels
// ===========================================================================
__global__ void prep_wh_kernel(const float* __restrict__ Wh) {
    int e = blockIdx.x * blockDim.x + threadIdx.x;  // 0 .. 262143
    int k = e >> 10, col = e & 1023;
    __half hi = __float2half(Wh[e]);
    int gate = col >> 8, j = col & 255;
    int jt = j >> 5, jw = (j >> 3) & 3, nl = j & 7;
    int kc = k >> 5, ks = (k >> 4) & 1, kk = k & 15;
    int gp = gate >> 1, gs = gate & 1;
    int lane = nl * 4 + ((kk & 7) >> 1);
    int reg  = kk >> 3;
    int hp   = kk & 1;
    int block = (jt * 4 + jw) * 32 + (kc * 2 + ks) * 2 + gp;
    __half* base = (__half*)g_Bfrag;
    base[((size_t)block * 32 + lane) * 8 + gs * 4 + reg * 2 + hp] = hi;
}

__global__ void prep_wxb_kernel(const float* __restrict__ Wx,
                                const float* __restrict__ bias) {
    int e = blockIdx.x * blockDim.x + threadIdx.x;  // 0 .. 131071
    g_Wxb[e] = Wx[e] + bias[e & 1023];
}

__global__ void prep_in_kernel(const int* __restrict__ inputs) {
    int i = blockIdx.x * blockDim.x + threadIdx.x;  // 0 .. 327679
    int b = i / SEQ, tt = i - b * SEQ;
    g_inT[tt * BATCH + b] = inputs[i];
}

__global__ void init_state_kernel() {
    int i = blockIdx.x * blockDim.x + threadIdx.x;   // 0 .. 524287
    if (i < 8192 * 32)
        ((uint4*)g_Afrag[0])[i] = make_uint4(0, 0, 0, 0);
    ((float4*)g_c)[i] = make_float4(0.f, 0.f, 0.f, 0.f);
}

// ===========================================================================
// LSTM step. CTA 256 thr = 8 warps (2 mw x 4 jw); warp tile M=32 x (4g x 8j).
// Single-pass fp16: z = a * b. A tile (64 batch x K = 32KB) staged in SMEM
// via cp.async; B frags LDG'd with register double-buffer (L1-resident).
// ===========================================================================
#define SMEM_TOTAL 32768

__global__ __launch_bounds__(256, 3) void lstm_step_kernel(int t) {
    extern __shared__ __align__(16) unsigned char smem[];
    const uint32_t sA = smem_to_u32(smem);
    const int tid  = threadIdx.x;
    const int lane = tid & 31, wid = tid >> 5;
    const int mw = wid >> 2;          // 0..1
    const int jw = wid & 3;           // 0..3
    const int bx = blockIdx.x;        // 0..127
    const int jt = blockIdx.y;        // 0..7

    // ---- stage A tile (64 blocks = 4 batch-groups) into SMEM: 2048 uint4
    {
        const uint4* Asrc = &g_Afrag[t & 1][bx * 64][0];
#pragma unroll
        for (int i = 0; i < 8; i++)
            CP_ASYNC16(sA + tid * 16 + i * 4096,
                       (const char*)(Asrc + i * 256 + tid));
        CP_COMMIT();
    }

    // ---- prefetch chars while A streams
    const int gq = lane >> 2, t4 = lane & 3;
    int ch[2][2];
#pragma unroll
    for (int mt = 0; mt < 2; mt++)
#pragma unroll
        for (int rr = 0; rr < 2; rr++)
            ch[mt][rr] = g_inT[t * BATCH + bx * 64 + mw * 32 + mt * 16 + gq + rr * 8];

    // ---- prefetch B iter 0 (2 blocks: gate pairs)
    const uint4* __restrict__ Bp = &g_Bfrag[(jt * 4 + jw) * 32][lane];
    uint4 bv0 = Bp[0], bv1 = Bp[32];

    CP_WAIT0();
    __syncthreads();

    float acc[2][4][4];
#pragma unroll
    for (int mt = 0; mt < 2; mt++)
#pragma unroll
        for (int g = 0; g < 4; g++)
#pragma unroll
            for (int e = 0; e < 4; e++) acc[mt][g][e] = 0.0f;

    // A smem: block (mw*2+mt)*16 + it, 512B/block
    const uint32_t aoff0 = sA + (mw * 2 + 0) * 16 * 512 + lane * 16;
    const uint32_t aoff1 = sA + (mw * 2 + 1) * 16 * 512 + lane * 16;

#pragma unroll 4
    for (int it = 0; it < 16; it++) {
        uint4 bn0, bn1;
        if (it < 15) {
            const uint4* p = Bp + (it + 1) * 64;
            bn0 = p[0]; bn1 = p[32];
        } else {
            bn0 = bv0; bn1 = bv1;
        }

        uint32_t ah[2][4];
        {
            uint32_t o = it * 512;
            LDS128(ah[0][0], ah[0][1], ah[0][2], ah[0][3], aoff0 + o);
            LDS128(ah[1][0], ah[1][1], ah[1][2], ah[1][3], aoff1 + o);
        }

#pragma unroll
        for (int mt = 0; mt < 2; mt++) {
            MMA16816(acc[mt][0], ah[mt], bv0.x, bv0.y);
            MMA16816(acc[mt][1], ah[mt], bv0.z, bv0.w);
            MMA16816(acc[mt][2], ah[mt], bv1.x, bv1.y);
            MMA16816(acc[mt][3], ah[mt], bv1.z, bv1.w);
        }
        bv0 = bn0; bv1 = bn1;
    }

    // ---- Epilogue: z = acc + Wxb[char] -> gates -> c; h stored as A-frags.
    const int jcol = jt * 32 + jw * 8 + t4 * 2;   // even
    // store block = grp*16 + jt*2 + (jw>>1); reg = rr + 2*(jw&1); lane==lane.
    const int blk_base = jt * 2 + (jw >> 1);
    uint32_t* __restrict__ Aout = (uint32_t*)g_Afrag[(t + 1) & 1];

#pragma unroll
    for (int mt = 0; mt < 2; mt++) {
        const int grp = bx * 4 + mw * 2 + mt;
#pragma unroll
        for (int rr = 0; rr < 2; rr++) {
            const int b = bx * 64 + mw * 32 + mt * 16 + gq + rr * 8;
            const float* wrow = g_Wxb + (size_t)ch[mt][rr] * 1024;
            float2 wx2[4];
#pragma unroll
            for (int g = 0; g < 4; g++)
                wx2[g] = *(const float2*)&wrow[g * 256 + jcol];
            float2 c2 = *(const float2*)&g_c[(size_t)b * HID + jcol];

            float cn[2], hn[2];
#pragma unroll
            for (int e = 0; e < 2; e++) {
                float zi = acc[mt][0][rr * 2 + e] + (e ? wx2[0].y : wx2[0].x);
                float zf = acc[mt][1][rr * 2 + e] + (e ? wx2[1].y : wx2[1].x);
                float zg = acc[mt][2][rr * 2 + e] + (e ? wx2[2].y : wx2[2].x);
                float zo = acc[mt][3][rr * 2 + e] + (e ? wx2[3].y : wx2[3].x);
                float ig = sigf(zi), fg = sigf(zf);
                float gg = tanh_(zg), og = sigf(zo);
                float cold = e ? c2.y : c2.x;
                float cc = fg * cold + ig * gg;
                cn[e] = cc;
                hn[e] = og * tanh_(cc);
            }
            *(float2*)&g_c[(size_t)b * HID + jcol] = make_float2(cn[0], cn[1]);

            __half2 phi = __halves2half2(__float2half(hn[0]), __float2half(hn[1]));
            const int reg = rr + 2 * (jw & 1);
            uint32_t idx = (uint32_t)(((grp * 16 + blk_base) * 32 + lane) * 4 + reg);
            Aout[idx] = *(uint32_t*)&phi;

            if (t == SEQ - 1)
                *(float2*)&g_hfin[(size_t)b * HID + jcol] = make_float2(hn[0], hn[1]);
        }
    }
}

// ===========================================================================
// Dense + softmax (reads g_hfin, float)
// ===========================================================================
#define DROWS 8

__global__ __launch_bounds__(128) void dense_softmax_kernel(
    const float* __restrict__ Wd,   // [256, 128]
    const float* __restrict__ bd,   // [128]
    float*       __restrict__ out)  // [BATCH, 128]
{
    const int b0  = blockIdx.x * DROWS;
    const int tid = threadIdx.x;

    __shared__ float hs[DROWS][HID];
    __shared__ float ls[DROWS][VOCAB];

#pragma unroll
    for (int s = 0; s < DROWS * HID / 128; s++) {
        int e = tid + s * 128;
        hs[e >> 8][e & 255] = g_hfin[(size_t)b0 * HID + e];
    }
    __syncthreads();

    float acc[DROWS];
    float bv = bd[tid];
#pragma unroll
    for (int r = 0; r < DROWS; r++) acc[r] = bv;

#pragma unroll 8
    for (int k = 0; k < HID; k++) {
        float w = Wd[k * VOCAB + tid];
#pragma unroll
        for (int r = 0; r < DROWS; r++) acc[r] += hs[r][k] * w;
    }

#pragma unroll
    for (int r = 0; r < DROWS; r++) ls[r][tid] = acc[r];
    __syncthreads();

    const int w = tid >> 5, lane = tid & 31;
#pragma unroll
    for (int rr = 0; rr < 2; rr++) {
        int r = w * 2 + rr;
        float v[4];
        float m = -1e30f;
#pragma unroll
        for (int q = 0; q < 4; q++) {
            v[q] = ls[r][lane + q * 32];
            m = fmaxf(m, v[q]);
        }
#pragma unroll
        for (int o = 16; o > 0; o >>= 1) m = fmaxf(m, __shfl_xor_sync(0xffffffffu, m, o));
        float s = 0.0f;
#pragma unroll
        for (int q = 0; q < 4; q++) {
            v[q] = __expf(v[q] - m);
            s += v[q];
        }
#pragma unroll
        for (int o = 16; o > 0; o >>= 1) s += __shfl_xor_sync(0xffffffffu, s, o);
        float inv = 1.0f / s;
#pragma unroll
        for (int q = 0; q < 4; q++)
            out[(b0 + r) * VOCAB + lane + q * 32] = v[q] * inv;
    }
}

// ===========================================================================
extern "C" void kernel_launch(void* const* d_in, const int* in_sizes, int n_in,
                              void* d_out, int out_size) {
    const int*   inputs = (const int*)d_in[0];
    const float* Wx     = (const float*)d_in[1];
    const float* Wh     = (const float*)d_in[2];
    const float* b      = (const float*)d_in[3];
    const float* Wd     = (const float*)d_in[4];
    const float* bd     = (const float*)d_in[5];
    float*       out    = (float*)d_out;

    cudaFuncSetAttribute(lstm_step_kernel,
                         cudaFuncAttributeMaxDynamicSharedMemorySize, SMEM_TOTAL);

    init_state_kernel<<<2048, 256>>>();
    prep_wh_kernel<<<1024, 256>>>(Wh);
    prep_wxb_kernel<<<512, 256>>>(Wx, b);
    prep_in_kernel<<<(BATCH * SEQ + 255) / 256, 256>>>(inputs);

    dim3 grid(BATCH / 64, 8);  // 128 x 8 = 1024 CTAs
    for (int t = 0; t < SEQ; t++)
        lstm_step_kernel<<<grid, 256, SMEM_TOTAL>>>(t);

    dense_softmax_kernel<<<BATCH / DROWS, 128>>>(Wd, bd, out);
}